// round 10
// baseline (speedup 1.0000x reference)
#include <cuda_runtime.h>
#include <cuda_bf16.h>
#include <cstdint>

#define NN 64
#define CC 128
#define FF 2048
#define MM 128
typedef unsigned long long u64;

__device__ __nv_bfloat16 g_Whi[(size_t)NN * CC * MM];
__device__ __nv_bfloat16 g_Wlo[(size_t)NN * CC * MM];

__device__ __forceinline__ uint32_t smem_u32(const void* p) {
    uint32_t a;
    asm("{ .reg .u64 t; cvta.to.shared.u64 t, %1; cvt.u32.u64 %0, t; }" : "=r"(a) : "l"(p));
    return a;
}
__device__ __forceinline__ void ldm_x4(uint32_t* r, uint32_t addr) {
    asm volatile("ldmatrix.sync.aligned.m8n8.x4.shared.b16 {%0,%1,%2,%3}, [%4];"
                 : "=r"(r[0]), "=r"(r[1]), "=r"(r[2]), "=r"(r[3]) : "r"(addr));
}
__device__ __forceinline__ void ldm_x4t(uint32_t* r, uint32_t addr) {
    asm volatile("ldmatrix.sync.aligned.m8n8.x4.trans.shared.b16 {%0,%1,%2,%3}, [%4];"
                 : "=r"(r[0]), "=r"(r[1]), "=r"(r[2]), "=r"(r[3]) : "r"(addr));
}
__device__ __forceinline__ void mma16816(float* d, const uint32_t* a,
                                         uint32_t b0, uint32_t b1) {
    asm volatile(
        "mma.sync.aligned.m16n8k16.row.col.f32.bf16.bf16.f32 "
        "{%0,%1,%2,%3}, {%4,%5,%6,%7}, {%8,%9}, {%0,%1,%2,%3};"
        : "+f"(d[0]), "+f"(d[1]), "+f"(d[2]), "+f"(d[3])
        : "r"(a[0]), "r"(a[1]), "r"(a[2]), "r"(a[3]), "r"(b0), "r"(b1));
}
__device__ __forceinline__ void cvt4(const float4 v, u64& hi, u64& lo) {
    __nv_bfloat162 h01 = __floats2bfloat162_rn(v.x, v.y);
    __nv_bfloat162 h23 = __floats2bfloat162_rn(v.z, v.w);
    float2 f01 = __bfloat1622float2(h01);
    float2 f23 = __bfloat1622float2(h23);
    __nv_bfloat162 l01 = __floats2bfloat162_rn(v.x - f01.x, v.y - f01.y);
    __nv_bfloat162 l23 = __floats2bfloat162_rn(v.z - f23.x, v.w - f23.y);
    hi = (u64)*(uint32_t*)&h01 | ((u64)*(uint32_t*)&h23 << 32);
    lo = (u64)*(uint32_t*)&l01 | ((u64)*(uint32_t*)&l23 << 32);
}

// ============================================================================
// k1: CTA per c, 512 threads (16 warps). S[64n,128m] = sum_f A_c[m,f]*X[n,c,f].
// Warp tile 16n x 32m (nb = w&3, mb = w>>2). K chunks of 64, double-buffered.
// Buffer (55296B, pitch 144): Ahi@0 Alo@18432 Xhi@36864 Xlo@46080; x2 buffers.
// Fused softmax (8 thr/row) -> split Whi/Wlo.
// ============================================================================
__global__ __launch_bounds__(512, 1) void k1_scores(const float* __restrict__ X,
                                                    const float* __restrict__ A) {
    extern __shared__ __align__(16) char sm1[];
    const uint32_t sB = smem_u32(sm1);
    const int tid = threadIdx.x, w = tid >> 5, lane = tid & 31;
    const int c = blockIdx.x;
    const int nb = w & 3, mb = w >> 2;

    // staging maps (512 threads)
    const int ar = tid >> 2, aq = tid & 3;   // A: row m (0..127), 16-float piece
    const int xr = tid >> 3, xq = tid & 7;   // X: row n (0..63), 8-float piece
    const float* Arow = A + ((size_t)c * MM + ar) * FF + aq * 16;
    const float* Xrow = X + ((size_t)xr * CC + c) * FF + xq * 8;

    // fragment bases (within buffer)
    const uint32_t xfrow = nb * 16 + (lane & 7) + ((lane >> 3) & 1) * 8;
    const uint32_t xfoff = 36864 + xfrow * 144 + ((lane >> 4) & 1) * 16;
    const uint32_t afrow = mb * 32 + (lane & 7) + ((lane >> 4) & 1) * 8;
    const uint32_t afoff = afrow * 144 + ((lane >> 3) & 1) * 16;

    float d[4][4];
#pragma unroll
    for (int t = 0; t < 4; t++)
#pragma unroll
        for (int i = 0; i < 4; i++) d[t][i] = 0.f;

    float4 ra[4], rx[2];
#pragma unroll
    for (int i = 0; i < 4; i++) ra[i] = *(const float4*)(Arow + i * 4);
#pragma unroll
    for (int i = 0; i < 2; i++) rx[i] = *(const float4*)(Xrow + i * 4);
    // chunk 0 -> buf0
#pragma unroll
    for (int i = 0; i < 4; i++) {
        u64 hi, lo; cvt4(ra[i], hi, lo);
        const uint32_t o = (uint32_t)(ar * 144 + aq * 32 + i * 8);
        *(u64*)(sm1 + o) = hi;  *(u64*)(sm1 + 18432 + o) = lo;
    }
#pragma unroll
    for (int i = 0; i < 2; i++) {
        u64 hi, lo; cvt4(rx[i], hi, lo);
        const uint32_t o = (uint32_t)(xr * 144 + xq * 16 + i * 8);
        *(u64*)(sm1 + 36864 + o) = hi;  *(u64*)(sm1 + 46080 + o) = lo;
    }
    // chunk 1 -> regs
#pragma unroll
    for (int i = 0; i < 4; i++) ra[i] = *(const float4*)(Arow + 64 + i * 4);
#pragma unroll
    for (int i = 0; i < 2; i++) rx[i] = *(const float4*)(Xrow + 64 + i * 4);
    __syncthreads();

    for (int ch = 0; ch < 32; ch++) {
        const int b = ch & 1;
        char* nbuf = sm1 + (b ^ 1) * 55296;
        if (ch < 31) {   // stage chunk ch+1
#pragma unroll
            for (int i = 0; i < 4; i++) {
                u64 hi, lo; cvt4(ra[i], hi, lo);
                const uint32_t o = (uint32_t)(ar * 144 + aq * 32 + i * 8);
                *(u64*)(nbuf + o) = hi;  *(u64*)(nbuf + 18432 + o) = lo;
            }
#pragma unroll
            for (int i = 0; i < 2; i++) {
                u64 hi, lo; cvt4(rx[i], hi, lo);
                const uint32_t o = (uint32_t)(xr * 144 + xq * 16 + i * 8);
                *(u64*)(nbuf + 36864 + o) = hi;  *(u64*)(nbuf + 46080 + o) = lo;
            }
        }
        if (ch < 30) {   // LDG chunk ch+2
            const int k0 = (ch + 2) * 64;
#pragma unroll
            for (int i = 0; i < 4; i++) ra[i] = *(const float4*)(Arow + k0 + i * 4);
#pragma unroll
            for (int i = 0; i < 2; i++) rx[i] = *(const float4*)(Xrow + k0 + i * 4);
        }
        const uint32_t B = sB + b * 55296;
#pragma unroll
        for (int ks = 0; ks < 4; ks++) {
            uint32_t xh[4], xl[4], ahf[8], alf[8];
            ldm_x4(xh, B + xfoff + ks * 32);
            ldm_x4(xl, B + xfoff + 9216 + ks * 32);
#pragma unroll
            for (int p = 0; p < 2; p++) ldm_x4(ahf + p * 4, B + afoff + p * 2304 + ks * 32);
#pragma unroll
            for (int p = 0; p < 2; p++) ldm_x4(alf + p * 4, B + afoff + 18432 + p * 2304 + ks * 32);
#pragma unroll
            for (int t = 0; t < 4; t++) mma16816(d[t], xh, ahf[t * 2], ahf[t * 2 + 1]);
#pragma unroll
            for (int t = 0; t < 4; t++) mma16816(d[t], xh, alf[t * 2], alf[t * 2 + 1]);
#pragma unroll
            for (int t = 0; t < 4; t++) mma16816(d[t], xl, ahf[t * 2], ahf[t * 2 + 1]);
        }
        __syncthreads();
    }

    // scores -> Ss[n][m] (pitch 132, reuses buf0)
    float* Ss = (float*)sm1;
    const int r0 = nb * 16 + (lane >> 2);
#pragma unroll
    for (int t = 0; t < 4; t++) {
        const int mcol = mb * 32 + t * 8 + (lane & 3) * 2;
        Ss[r0 * 132 + mcol]           = d[t][0];
        Ss[r0 * 132 + mcol + 1]       = d[t][1];
        Ss[(r0 + 8) * 132 + mcol]     = d[t][2];
        Ss[(r0 + 8) * 132 + mcol + 1] = d[t][3];
    }
    __syncthreads();

    // softmax: 8 threads per row
    {
        const int row = tid >> 3, q = tid & 7;
        float* Rs = Ss + row * 132 + q * 16;
        float mx = Rs[0];
#pragma unroll
        for (int m = 1; m < 16; m++) mx = fmaxf(mx, Rs[m]);
        mx = fmaxf(mx, __shfl_xor_sync(0xffffffffu, mx, 1));
        mx = fmaxf(mx, __shfl_xor_sync(0xffffffffu, mx, 2));
        mx = fmaxf(mx, __shfl_xor_sync(0xffffffffu, mx, 4));
        float sum = 0.f;
#pragma unroll
        for (int m = 0; m < 16; m++) { float e = __expf(Rs[m] - mx); sum += e; Rs[m] = e; }
        sum += __shfl_xor_sync(0xffffffffu, sum, 1);
        sum += __shfl_xor_sync(0xffffffffu, sum, 2);
        sum += __shfl_xor_sync(0xffffffffu, sum, 4);
        const float inv = 1.f / sum;
        __nv_bfloat16* whi = g_Whi + ((size_t)row * CC + c) * MM + q * 16;
        __nv_bfloat16* wlo = g_Wlo + ((size_t)row * CC + c) * MM + q * 16;
#pragma unroll
        for (int m = 0; m < 16; m += 2) {
            float w0 = Rs[m] * inv, w1 = Rs[m + 1] * inv;
            __nv_bfloat162 h = __floats2bfloat162_rn(w0, w1);
            float2 hf = __bfloat1622float2(h);
            __nv_bfloat162 l = __floats2bfloat162_rn(w0 - hf.x, w1 - hf.y);
            *(__nv_bfloat162*)(whi + m) = h;
            *(__nv_bfloat162*)(wlo + m) = l;
        }
    }
}

// ============================================================================
// k2: grid (2 f-halves, 64 n), 512 threads (16 warps). out = W_n * X_n.
// Warp tile 16c x 32f: cb = w&7, fb = w>>3. W hi+lo fragments in registers.
// X tiles [m=128][f=64] double-buffered (pitch 144): buf b @ b*36864,
// hi@0 lo@18432. W one-time stage (pitch 272) reuses same smem before loop.
// ============================================================================
__global__ __launch_bounds__(512, 1) void k2_combine(const float* __restrict__ X,
                                                     float* __restrict__ Out) {
    extern __shared__ __align__(16) char sm2[];
    const uint32_t sB = smem_u32(sm2);
    const int tid = threadIdx.x, w = tid >> 5, lane = tid & 31;
    const int n = blockIdx.y, fh = blockIdx.x;
    const int cb = w & 7, fb = w >> 3;

    // ---- one-time W stage (pitch 272) ----
    {
        const int cr2 = tid >> 2, q2 = tid & 3;
        const __nv_bfloat16* WhiG = g_Whi + ((size_t)n * CC + cr2) * MM + q2 * 32;
        const __nv_bfloat16* WloG = g_Wlo + ((size_t)n * CC + cr2) * MM + q2 * 32;
#pragma unroll
        for (int i = 0; i < 8; i++) {
            const uint32_t o = (uint32_t)(cr2 * 272 + q2 * 64 + i * 8);
            *(u64*)(sm2 + o)         = *(const u64*)(WhiG + i * 4);
            *(u64*)(sm2 + 34816 + o) = *(const u64*)(WloG + i * 4);
        }
    }
    __syncthreads();
    uint32_t wh[32], wl[32];
    {
        const uint32_t wrow = cb * 16 + (lane & 7) + ((lane >> 3) & 1) * 8;
        const uint32_t wboff = wrow * 272 + ((lane >> 4) & 1) * 16;
#pragma unroll
        for (int ks = 0; ks < 8; ks++) {
            ldm_x4(wh + ks * 4, sB + wboff + ks * 32);
            ldm_x4(wl + ks * 4, sB + 34816 + wboff + ks * 32);
        }
    }
    __syncthreads();   // smem free for X buffers

    const uint32_t xmrow = (lane & 7) + ((lane >> 3) & 1) * 8;
    const uint32_t xboff = xmrow * 144 + ((lane >> 4) & 1) * 16 + fb * 64;
    const int cr = tid >> 2, q = tid & 3;   // X stage: m row, 16-f piece
    const float* Xrow2 = X + ((size_t)n * CC + cr) * FF + fh * 1024 + q * 16;
    float* Ob = Out + ((size_t)n * CC) * FF + fh * 1024;

    float4 rx[4];
#pragma unroll
    for (int i = 0; i < 4; i++) rx[i] = *(const float4*)(Xrow2 + i * 4);
#pragma unroll
    for (int i = 0; i < 4; i++) {
        u64 hi, lo; cvt4(rx[i], hi, lo);
        const uint32_t o = (uint32_t)(cr * 144 + q * 32 + i * 8);
        *(u64*)(sm2 + o) = hi;  *(u64*)(sm2 + 18432 + o) = lo;
    }
#pragma unroll
    for (int i = 0; i < 4; i++) rx[i] = *(const float4*)(Xrow2 + 64 + i * 4);
    __syncthreads();

    for (int t = 0; t < 16; t++) {
        const int b = t & 1;
        char* nbuf = sm2 + (b ^ 1) * 36864;
        if (t < 15) {   // stage tile t+1
#pragma unroll
            for (int i = 0; i < 4; i++) {
                u64 hi, lo; cvt4(rx[i], hi, lo);
                const uint32_t o = (uint32_t)(cr * 144 + q * 32 + i * 8);
                *(u64*)(nbuf + o) = hi;  *(u64*)(nbuf + 18432 + o) = lo;
            }
        }
        if (t < 14) {   // LDG tile t+2
#pragma unroll
            for (int i = 0; i < 4; i++)
                rx[i] = *(const float4*)(Xrow2 + (t + 2) * 64 + i * 4);
        }

        float d[4][4];
#pragma unroll
        for (int ft = 0; ft < 4; ft++)
#pragma unroll
            for (int i = 0; i < 4; i++) d[ft][i] = 0.f;

        const uint32_t B = sB + b * 36864;
#pragma unroll
        for (int ks = 0; ks < 8; ks++) {
            uint32_t xh[8], xl[8];
#pragma unroll
            for (int j = 0; j < 2; j++) ldm_x4t(xh + j * 4, B + xboff + ks * 2304 + j * 32);
#pragma unroll
            for (int j = 0; j < 2; j++) ldm_x4t(xl + j * 4, B + xboff + 18432 + ks * 2304 + j * 32);
#pragma unroll
            for (int ft = 0; ft < 4; ft++) mma16816(d[ft], wh + ks * 4, xh[ft * 2], xh[ft * 2 + 1]);
#pragma unroll
            for (int ft = 0; ft < 4; ft++) mma16816(d[ft], wh + ks * 4, xl[ft * 2], xl[ft * 2 + 1]);
#pragma unroll
            for (int ft = 0; ft < 4; ft++) mma16816(d[ft], wl + ks * 4, xh[ft * 2], xh[ft * 2 + 1]);
        }

        const int crow = cb * 16 + (lane >> 2);
#pragma unroll
        for (int ft = 0; ft < 4; ft++) {
            const int f = t * 64 + fb * 32 + ft * 8 + (lane & 3) * 2;
            *(float2*)(Ob + (size_t)crow * FF + f)       = make_float2(d[ft][0], d[ft][1]);
            *(float2*)(Ob + (size_t)(crow + 8) * FF + f) = make_float2(d[ft][2], d[ft][3]);
        }
        __syncthreads();
    }
}

extern "C" void kernel_launch(void* const* d_in, const int* in_sizes, int n_in,
                              void* d_out, int out_size) {
    const float* X = (const float*)d_in[0];
    const float* A = (const float*)d_in[1];
    float* Out = (float*)d_out;

    cudaFuncSetAttribute(k1_scores, cudaFuncAttributeMaxDynamicSharedMemorySize, 110592);
    cudaFuncSetAttribute(k2_combine, cudaFuncAttributeMaxDynamicSharedMemorySize, 73728);

    k1_scores<<<CC, 512, 110592>>>(X, A);
    dim3 g2(2, NN);
    k2_combine<<<g2, 512, 73728>>>(X, Out);
}

// round 12
// speedup vs baseline: 1.7887x; 1.7887x over previous
#include <cuda_runtime.h>
#include <cuda_fp16.h>
#include <cstdint>

#define NN 64
#define CC 128
#define FF 2048
#define MM 128
typedef unsigned long long u64;

// softmax weights, split fp16 (hi + lo), [n][c][m]
__device__ __half g_Whi[(size_t)NN * CC * MM];
__device__ __half g_Wlo[(size_t)NN * CC * MM];

__device__ __forceinline__ uint32_t smem_u32(const void* p) {
    uint32_t a;
    asm("{ .reg .u64 t; cvta.to.shared.u64 t, %1; cvt.u32.u64 %0, t; }" : "=r"(a) : "l"(p));
    return a;
}
__device__ __forceinline__ void ldm_x4(uint32_t* r, uint32_t addr) {
    asm volatile("ldmatrix.sync.aligned.m8n8.x4.shared.b16 {%0,%1,%2,%3}, [%4];"
                 : "=r"(r[0]), "=r"(r[1]), "=r"(r[2]), "=r"(r[3]) : "r"(addr));
}
__device__ __forceinline__ void ldm_x4t(uint32_t* r, uint32_t addr) {
    asm volatile("ldmatrix.sync.aligned.m8n8.x4.trans.shared.b16 {%0,%1,%2,%3}, [%4];"
                 : "=r"(r[0]), "=r"(r[1]), "=r"(r[2]), "=r"(r[3]) : "r"(addr));
}
__device__ __forceinline__ void mma16816(float* d, const uint32_t* a,
                                         uint32_t b0, uint32_t b1) {
    asm volatile(
        "mma.sync.aligned.m16n8k16.row.col.f32.f16.f16.f32 "
        "{%0,%1,%2,%3}, {%4,%5,%6,%7}, {%8,%9}, {%0,%1,%2,%3};"
        : "+f"(d[0]), "+f"(d[1]), "+f"(d[2]), "+f"(d[3])
        : "r"(a[0]), "r"(a[1]), "r"(a[2]), "r"(a[3]), "r"(b0), "r"(b1));
}
// float4 -> 4 packed fp16 (optionally scaled)
__device__ __forceinline__ u64 cvt4h(const float4 v, float s) {
    __half2 h01 = __floats2half2_rn(v.x * s, v.y * s);
    __half2 h23 = __floats2half2_rn(v.z * s, v.w * s);
    return (u64)*(uint32_t*)&h01 | ((u64)*(uint32_t*)&h23 << 32);
}

#define ASCALE 256.0f
#define INV_ASCALE (1.0f / 256.0f)

// ============================================================================
// k1: CTA per c, 256 threads (8 warps). S[64n,128m] = sum_f A_c[m,f]*X[n,c,f].
// SINGLE fp16 term (A scaled x256). K chunks of 64, double-buffered.
// Buffer (27648B, pitch 144): Ah@0 (128x144), Xh@18432 (64x144); x2 buffers.
// Warp tile 16n x 64m (nb = w&3, mb = w>>2). Fused softmax -> split Whi/Wlo.
// ============================================================================
__global__ __launch_bounds__(256, 1) void k1_scores(const float* __restrict__ X,
                                                    const float* __restrict__ A) {
    extern __shared__ __align__(16) char sm1[];
    const uint32_t sB = smem_u32(sm1);
    const int tid = threadIdx.x, w = tid >> 5, lane = tid & 31;
    const int c = blockIdx.x;
    const int nb = w & 3, mb = w >> 2;

    const int ar = tid >> 1, ah = tid & 1;   // A: row m, 32-float half of 64k
    const int xr = tid >> 2, xq = tid & 3;   // X: row n, 16-float quarter
    const float* Arow = A + ((size_t)c * MM + ar) * FF + ah * 32;
    const float* Xrow = X + ((size_t)xr * CC + c) * FF + xq * 16;

    // fragment bases (within a buffer) — proven R9 mapping
    const uint32_t xfrow = nb * 16 + (lane & 7) + ((lane >> 3) & 1) * 8;
    const uint32_t xfoff = 18432 + xfrow * 144 + ((lane >> 4) & 1) * 16;
    const uint32_t afrow = mb * 64 + (lane & 7) + ((lane >> 4) & 1) * 8;
    const uint32_t afoff = afrow * 144 + ((lane >> 3) & 1) * 16;

    float d[8][4];
#pragma unroll
    for (int t = 0; t < 8; t++)
#pragma unroll
        for (int i = 0; i < 4; i++) d[t][i] = 0.f;

    float4 ra[8], rx[4];
#pragma unroll
    for (int i = 0; i < 8; i++) ra[i] = *(const float4*)(Arow + i * 4);
#pragma unroll
    for (int i = 0; i < 4; i++) rx[i] = *(const float4*)(Xrow + i * 4);
    // chunk 0 -> buf0
#pragma unroll
    for (int i = 0; i < 8; i++)
        *(u64*)(sm1 + (uint32_t)(ar * 144 + ah * 64 + i * 8)) = cvt4h(ra[i], ASCALE);
#pragma unroll
    for (int i = 0; i < 4; i++)
        *(u64*)(sm1 + 18432 + (uint32_t)(xr * 144 + xq * 32 + i * 8)) = cvt4h(rx[i], 1.f);
    // chunk 1 -> regs
#pragma unroll
    for (int i = 0; i < 8; i++) ra[i] = *(const float4*)(Arow + 64 + i * 4);
#pragma unroll
    for (int i = 0; i < 4; i++) rx[i] = *(const float4*)(Xrow + 64 + i * 4);
    __syncthreads();

    for (int ch = 0; ch < 32; ch++) {
        const int b = ch & 1;
        char* nbuf = sm1 + (b ^ 1) * 27648;
        if (ch < 31) {   // stage chunk ch+1 into other buffer
#pragma unroll
            for (int i = 0; i < 8; i++)
                *(u64*)(nbuf + (uint32_t)(ar * 144 + ah * 64 + i * 8)) = cvt4h(ra[i], ASCALE);
#pragma unroll
            for (int i = 0; i < 4; i++)
                *(u64*)(nbuf + 18432 + (uint32_t)(xr * 144 + xq * 32 + i * 8)) = cvt4h(rx[i], 1.f);
        }
        if (ch < 30) {   // LDG chunk ch+2
            const int k0 = (ch + 2) * 64;
#pragma unroll
            for (int i = 0; i < 8; i++) ra[i] = *(const float4*)(Arow + k0 + i * 4);
#pragma unroll
            for (int i = 0; i < 4; i++) rx[i] = *(const float4*)(Xrow + k0 + i * 4);
        }
        const uint32_t B = sB + b * 27648;
#pragma unroll
        for (int ks = 0; ks < 4; ks++) {
            uint32_t xh[4], ahf[16];
            ldm_x4(xh, B + xfoff + ks * 32);
#pragma unroll
            for (int p = 0; p < 4; p++) ldm_x4(ahf + p * 4, B + afoff + p * 2304 + ks * 32);
#pragma unroll
            for (int t = 0; t < 8; t++) mma16816(d[t], xh, ahf[t * 2], ahf[t * 2 + 1]);
        }
        __syncthreads();
    }

    // scores -> Ss[n][m] (pitch 132, reuses buf0)
    float* Ss = (float*)sm1;
    const int r0 = nb * 16 + (lane >> 2);
#pragma unroll
    for (int t = 0; t < 8; t++) {
        const int mcol = mb * 64 + t * 8 + (lane & 3) * 2;
        Ss[r0 * 132 + mcol]           = d[t][0];
        Ss[r0 * 132 + mcol + 1]       = d[t][1];
        Ss[(r0 + 8) * 132 + mcol]     = d[t][2];
        Ss[(r0 + 8) * 132 + mcol + 1] = d[t][3];
    }
    __syncthreads();

    // softmax: 4 threads per row (scores carry x256 scale -> undo before exp)
    {
        const int row = tid >> 2, q = tid & 3;
        float* Rs = Ss + row * 132 + q * 32;
        float mx = Rs[0] * INV_ASCALE;
#pragma unroll 8
        for (int m = 1; m < 32; m++) mx = fmaxf(mx, Rs[m] * INV_ASCALE);
        mx = fmaxf(mx, __shfl_xor_sync(0xffffffffu, mx, 1));
        mx = fmaxf(mx, __shfl_xor_sync(0xffffffffu, mx, 2));
        float sum = 0.f;
#pragma unroll 8
        for (int m = 0; m < 32; m++) {
            float e = __expf(Rs[m] * INV_ASCALE - mx);
            sum += e;
            Rs[m] = e;
        }
        sum += __shfl_xor_sync(0xffffffffu, sum, 1);
        sum += __shfl_xor_sync(0xffffffffu, sum, 2);
        const float inv = 1.f / sum;
        __half* whi = g_Whi + ((size_t)row * CC + c) * MM + q * 32;
        __half* wlo = g_Wlo + ((size_t)row * CC + c) * MM + q * 32;
#pragma unroll 4
        for (int m = 0; m < 32; m += 2) {
            float w0 = Rs[m] * inv, w1 = Rs[m + 1] * inv;
            __half2 h = __floats2half2_rn(w0, w1);
            float2 hf = __half22float2(h);
            __half2 l = __floats2half2_rn(w0 - hf.x, w1 - hf.y);
            *(__half2*)(whi + m) = h;
            *(__half2*)(wlo + m) = l;
        }
    }
}

// ============================================================================
// k2: grid (2 f-halves, 64 n), 256 threads. out[c,f] = sum_m W[n,c,m]*X[n,m,f].
// 2-term: (Whi + Wlo) * Xfp16. W hi+lo fragments in registers (one-time stage,
// pitch 272: Whi@0, Wlo@34816). X tiles [m=128][f=64] single fp16,
// double-buffered (pitch 144, 18432B each). Dynamic smem 69632.
// Warp tile 16c x 64f; one sync per tile; stage(t+1)+LDG(t+2) overlap MMA(t).
// ============================================================================
__global__ __launch_bounds__(256, 1) void k2_combine(const float* __restrict__ X,
                                                     float* __restrict__ Out) {
    extern __shared__ __align__(16) char sm2[];
    const uint32_t sB = smem_u32(sm2);
    const int tid = threadIdx.x, w = tid >> 5, lane = tid & 31;
    const int n = blockIdx.y, fh = blockIdx.x;

    const int cr = tid >> 1, hh = tid & 1;
    {   // one-time W stage (fp16 hi/lo, pitch 272)
        const __half* WhiG = g_Whi + ((size_t)n * CC + cr) * MM + hh * 64;
        const __half* WloG = g_Wlo + ((size_t)n * CC + cr) * MM + hh * 64;
#pragma unroll
        for (int i = 0; i < 16; i++) {
            const uint32_t o = (uint32_t)(cr * 272 + hh * 128 + i * 8);
            *(u64*)(sm2 + o)         = *(const u64*)(WhiG + i * 4);
            *(u64*)(sm2 + 34816 + o) = *(const u64*)(WloG + i * 4);
        }
    }
    __syncthreads();
    uint32_t wh[32], wl[32];
    {
        const uint32_t wrow = w * 16 + (lane & 7) + ((lane >> 3) & 1) * 8;
        const uint32_t wboff = wrow * 272 + ((lane >> 4) & 1) * 16;
#pragma unroll
        for (int ks = 0; ks < 8; ks++) {
            ldm_x4(wh + ks * 4, sB + wboff + ks * 32);
            ldm_x4(wl + ks * 4, sB + 34816 + wboff + ks * 32);
        }
    }
    __syncthreads();   // W in regs; smem free for X buffers

    const uint32_t xmrow = (lane & 7) + ((lane >> 3) & 1) * 8;
    const uint32_t xboff = xmrow * 144 + ((lane >> 4) & 1) * 16;
    const float* Xrow2 = X + ((size_t)n * CC + cr) * FF + fh * 1024 + hh * 32;
    float* Ob = Out + ((size_t)n * CC) * FF + fh * 1024;

    float4 rx[8];
#pragma unroll
    for (int i = 0; i < 8; i++) rx[i] = *(const float4*)(Xrow2 + i * 4);
#pragma unroll
    for (int i = 0; i < 8; i++)
        *(u64*)(sm2 + (uint32_t)(cr * 144 + hh * 64 + i * 8)) = cvt4h(rx[i], 1.f);
#pragma unroll
    for (int i = 0; i < 8; i++) rx[i] = *(const float4*)(Xrow2 + 64 + i * 4);
    __syncthreads();

    for (int t = 0; t < 16; t++) {
        const int b = t & 1;
        char* nbuf = sm2 + (b ^ 1) * 18432;
        if (t < 15) {   // stage tile t+1
#pragma unroll
            for (int i = 0; i < 8; i++)
                *(u64*)(nbuf + (uint32_t)(cr * 144 + hh * 64 + i * 8)) = cvt4h(rx[i], 1.f);
        }
        if (t < 14) {   // LDG tile t+2
#pragma unroll
            for (int i = 0; i < 8; i++)
                rx[i] = *(const float4*)(Xrow2 + (t + 2) * 64 + i * 4);
        }

        float d[8][4];
#pragma unroll
        for (int ft = 0; ft < 8; ft++)
#pragma unroll
            for (int i = 0; i < 4; i++) d[ft][i] = 0.f;

        const uint32_t B = sB + b * 18432;
#pragma unroll
        for (int ks = 0; ks < 8; ks++) {
            uint32_t xh[16];
#pragma unroll
            for (int j = 0; j < 4; j++) ldm_x4t(xh + j * 4, B + xboff + ks * 2304 + j * 32);
#pragma unroll
            for (int ft = 0; ft < 8; ft++) mma16816(d[ft], wh + ks * 4, xh[ft * 2], xh[ft * 2 + 1]);
#pragma unroll
            for (int ft = 0; ft < 8; ft++) mma16816(d[ft], wl + ks * 4, xh[ft * 2], xh[ft * 2 + 1]);
        }

        const int crow = w * 16 + (lane >> 2);
#pragma unroll
        for (int ft = 0; ft < 8; ft++) {
            const int f = t * 64 + ft * 8 + (lane & 3) * 2;
            *(float2*)(Ob + (size_t)crow * FF + f)       = make_float2(d[ft][0], d[ft][1]);
            *(float2*)(Ob + (size_t)(crow + 8) * FF + f) = make_float2(d[ft][2], d[ft][3]);
        }
        __syncthreads();
    }
}

extern "C" void kernel_launch(void* const* d_in, const int* in_sizes, int n_in,
                              void* d_out, int out_size) {
    const float* X = (const float*)d_in[0];
    const float* A = (const float*)d_in[1];
    float* Out = (float*)d_out;

    cudaFuncSetAttribute(k1_scores, cudaFuncAttributeMaxDynamicSharedMemorySize, 55296);
    cudaFuncSetAttribute(k2_combine, cudaFuncAttributeMaxDynamicSharedMemorySize, 69632);

    k1_scores<<<CC, 256, 55296>>>(X, A);
    dim3 g2(2, NN);
    k2_combine<<<g2, 256, 69632>>>(X, Out);
}